// round 1
// baseline (speedup 1.0000x reference)
#include <cuda_runtime.h>
#include <cuda_bf16.h>

#define N_NODES 100000
#define N_EDGES 1600000
#define IN_DIM 32
#define OUT_DIM 64
#define N_REL 8
#define K_DIM (N_REL * IN_DIM)   // 256
#define EPS 1e-10f

// Scratch (alloc-free rule: __device__ globals)
__device__ float g_num[(size_t)N_NODES * K_DIM];   // [node][rel][32]
__device__ float g_den[(size_t)N_NODES * N_REL];   // [node][rel]

// ---------------------------------------------------------------------------
// Kernel 1: zero the scratch accumulators (float4 stores)
// ---------------------------------------------------------------------------
__global__ void zero_kernel() {
    const int idx = blockIdx.x * blockDim.x + threadIdx.x;
    const int stride = gridDim.x * blockDim.x;
    float4 z = make_float4(0.f, 0.f, 0.f, 0.f);
    float4* n4 = reinterpret_cast<float4*>(g_num);
    const int nn = N_NODES * (K_DIM / 4);          // 6.4M float4
    for (int i = idx; i < nn; i += stride) n4[i] = z;
    float4* d4 = reinterpret_cast<float4*>(g_den);
    const int nd = N_NODES * (N_REL / 4);          // 200K float4
    for (int i = idx; i < nd; i += stride) d4[i] = z;
}

// ---------------------------------------------------------------------------
// Kernel 2: edge scatter. One thread per edge.
//   num[dst, rel, :] += x[src, :] * w   (vectorized red.global.add.v4.f32)
//   den[dst, rel]    += w
// ---------------------------------------------------------------------------
__global__ void scatter_kernel(const int* __restrict__ edge_list,
                               const float* __restrict__ edge_weight,
                               const float* __restrict__ x) {
    const int e = blockIdx.x * blockDim.x + threadIdx.x;
    if (e >= N_EDGES) return;
    const int src = edge_list[3 * e + 0];
    const int dst = edge_list[3 * e + 1];
    const int rel = edge_list[3 * e + 2];
    const float w = edge_weight[e];

    const float4* xr = reinterpret_cast<const float4*>(x + (size_t)src * IN_DIM);
    float* base = g_num + (size_t)dst * K_DIM + rel * IN_DIM;

#pragma unroll
    for (int i = 0; i < IN_DIM / 4; i++) {
        float4 v = xr[i];
        asm volatile(
            "red.global.add.v4.f32 [%0], {%1, %2, %3, %4};"
            :: "l"(base + i * 4),
               "f"(v.x * w), "f"(v.y * w), "f"(v.z * w), "f"(v.w * w)
            : "memory");
    }
    atomicAdd(g_den + (size_t)dst * N_REL + rel, w);
}

// ---------------------------------------------------------------------------
// Kernel 3: fused normalize + GEMM + bias + ReLU.
//   out[n, j] = relu( sum_k (num[n,k]/(den[n,k/32]+eps)) * Wl[k,j]
//                   + sum_k x[n,k] * Ws[k,j] + bl[j] + bs[j] )
// Persistent blocks; W cached in SMEM; 16 nodes per tile; each thread owns
// one output column j for 4 nodes (R=4 reuse of each W element).
// ---------------------------------------------------------------------------
#define GEMM_THREADS 256
#define TILE_NODES 16
#define GEMM_BLOCKS 304

__global__ __launch_bounds__(GEMM_THREADS, 2)
void gemm_kernel(const float* __restrict__ x,
                 const float* __restrict__ Wl,
                 const float* __restrict__ bl,
                 const float* __restrict__ Ws,
                 const float* __restrict__ bs,
                 float* __restrict__ out) {
    extern __shared__ float sm[];
    float* sWl   = sm;                       // 256*64 = 16384
    float* sWs   = sWl + K_DIM * OUT_DIM;    // 32*64  = 2048
    float* sB    = sWs + IN_DIM * OUT_DIM;   // 64
    float* sDinv = sB + OUT_DIM;             // 16*8   = 128
    float* sU    = sDinv + TILE_NODES * N_REL;        // 16*256 = 4096
    float* sX    = sU + TILE_NODES * K_DIM;           // 16*32  = 512

    const int tid = threadIdx.x;
    for (int i = tid; i < K_DIM * OUT_DIM; i += GEMM_THREADS) sWl[i] = Wl[i];
    for (int i = tid; i < IN_DIM * OUT_DIM; i += GEMM_THREADS) sWs[i] = Ws[i];
    if (tid < OUT_DIM) sB[tid] = bl[tid] + bs[tid];
    __syncthreads();

    const int j = tid & 63;     // output column
    const int g = tid >> 6;     // node subgroup 0..3 (4 nodes each)

    for (int tile = blockIdx.x * TILE_NODES; tile < N_NODES;
         tile += gridDim.x * TILE_NODES) {

        // --- stage den^-1 ---
        for (int i = tid; i < TILE_NODES * N_REL; i += GEMM_THREADS)
            sDinv[i] = 1.0f / (g_den[(size_t)tile * N_REL + i] + EPS);
        __syncthreads();

        // --- stage normalized update + x rows ---
        for (int i = tid; i < TILE_NODES * K_DIM; i += GEMM_THREADS) {
            const int r = i >> 8;          // node in tile
            const int k = i & 255;
            sU[i] = g_num[(size_t)(tile + r) * K_DIM + k] *
                    sDinv[r * N_REL + (k >> 5)];
        }
        for (int i = tid; i < TILE_NODES * IN_DIM; i += GEMM_THREADS)
            sX[i] = x[(size_t)tile * IN_DIM + i];
        __syncthreads();

        // --- compute: 4 nodes per thread, column j ---
        float acc0 = 0.f, acc1 = 0.f, acc2 = 0.f, acc3 = 0.f;
        const float4* sU4 = reinterpret_cast<const float4*>(sU);
        const int n0 = g * 4;

#pragma unroll 4
        for (int k4 = 0; k4 < K_DIM / 4; k4++) {
            const float4 u0 = sU4[(n0 + 0) * (K_DIM / 4) + k4];
            const float4 u1 = sU4[(n0 + 1) * (K_DIM / 4) + k4];
            const float4 u2 = sU4[(n0 + 2) * (K_DIM / 4) + k4];
            const float4 u3 = sU4[(n0 + 3) * (K_DIM / 4) + k4];
            const float w0 = sWl[(k4 * 4 + 0) * OUT_DIM + j];
            const float w1 = sWl[(k4 * 4 + 1) * OUT_DIM + j];
            const float w2 = sWl[(k4 * 4 + 2) * OUT_DIM + j];
            const float w3 = sWl[(k4 * 4 + 3) * OUT_DIM + j];
            acc0 += u0.x * w0 + u0.y * w1 + u0.z * w2 + u0.w * w3;
            acc1 += u1.x * w0 + u1.y * w1 + u1.z * w2 + u1.w * w3;
            acc2 += u2.x * w0 + u2.y * w1 + u2.z * w2 + u2.w * w3;
            acc3 += u3.x * w0 + u3.y * w1 + u3.z * w2 + u3.w * w3;
        }

        const float4* sX4 = reinterpret_cast<const float4*>(sX);
#pragma unroll
        for (int k4 = 0; k4 < IN_DIM / 4; k4++) {
            const float4 u0 = sX4[(n0 + 0) * (IN_DIM / 4) + k4];
            const float4 u1 = sX4[(n0 + 1) * (IN_DIM / 4) + k4];
            const float4 u2 = sX4[(n0 + 2) * (IN_DIM / 4) + k4];
            const float4 u3 = sX4[(n0 + 3) * (IN_DIM / 4) + k4];
            const float w0 = sWs[(k4 * 4 + 0) * OUT_DIM + j];
            const float w1 = sWs[(k4 * 4 + 1) * OUT_DIM + j];
            const float w2 = sWs[(k4 * 4 + 2) * OUT_DIM + j];
            const float w3 = sWs[(k4 * 4 + 3) * OUT_DIM + j];
            acc0 += u0.x * w0 + u0.y * w1 + u0.z * w2 + u0.w * w3;
            acc1 += u1.x * w0 + u1.y * w1 + u1.z * w2 + u1.w * w3;
            acc2 += u2.x * w0 + u2.y * w1 + u2.z * w2 + u2.w * w3;
            acc3 += u3.x * w0 + u3.y * w1 + u3.z * w2 + u3.w * w3;
        }

        const float b = sB[j];
        const int nbase = tile + n0;
        out[(size_t)(nbase + 0) * OUT_DIM + j] = fmaxf(acc0 + b, 0.f);
        out[(size_t)(nbase + 1) * OUT_DIM + j] = fmaxf(acc1 + b, 0.f);
        out[(size_t)(nbase + 2) * OUT_DIM + j] = fmaxf(acc2 + b, 0.f);
        out[(size_t)(nbase + 3) * OUT_DIM + j] = fmaxf(acc3 + b, 0.f);

        __syncthreads();   // protect sU/sX before next tile overwrites
    }
}

// ---------------------------------------------------------------------------
// Launch
// ---------------------------------------------------------------------------
extern "C" void kernel_launch(void* const* d_in, const int* in_sizes, int n_in,
                              void* d_out, int out_size) {
    const float* x        = (const float*)d_in[0];
    const int*   edges    = (const int*)  d_in[1];
    const float* ew       = (const float*)d_in[2];
    const float* Wl       = (const float*)d_in[3];
    const float* bl       = (const float*)d_in[4];
    const float* Ws       = (const float*)d_in[5];
    const float* bs       = (const float*)d_in[6];
    float*       out      = (float*)d_out;

    // zero accumulators
    zero_kernel<<<2048, 256>>>();

    // edge scatter
    scatter_kernel<<<(N_EDGES + 255) / 256, 256>>>(edges, ew, x);

    // fused normalize + GEMM + ReLU
    const int smem_floats = K_DIM * OUT_DIM + IN_DIM * OUT_DIM + OUT_DIM +
                            TILE_NODES * N_REL + TILE_NODES * K_DIM +
                            TILE_NODES * IN_DIM;
    const int smem_bytes = smem_floats * (int)sizeof(float);
    cudaFuncSetAttribute(gemm_kernel,
                         cudaFuncAttributeMaxDynamicSharedMemorySize,
                         smem_bytes);
    gemm_kernel<<<GEMM_BLOCKS, GEMM_THREADS, smem_bytes>>>(x, Wl, bl, Ws, bs, out);
}

// round 3
// speedup vs baseline: 1.4412x; 1.4412x over previous
#include <cuda_runtime.h>
#include <cstdint>

#define N_NODES 100000
#define N_EDGES 1600000
#define IN_DIM 32
#define OUT_DIM 64
#define N_REL 8
#define K_DIM (N_REL * IN_DIM)   // 256
#define K_TOT 288                // 256 (update) + 32 (x)
#define N_KSTEP (K_TOT / 8)      // 36
#define EPS 1e-10f

static constexpr int NTILES = (N_NODES + 127) / 128;   // 782

// Scratch (alloc-free rule: __device__ globals)
__device__ float g_num[(size_t)N_NODES * K_DIM];
__device__ float g_den[(size_t)N_NODES * N_REL];

__device__ __forceinline__ float to_tf32(float v) {
    uint32_t r;
    asm("cvt.rna.tf32.f32 %0, %1;" : "=r"(r) : "f"(v));
    return __uint_as_float(r);
}

// ---------------------------------------------------------------------------
// Kernel 1: edge scatter. One thread per edge; vector reductions.
// ---------------------------------------------------------------------------
__global__ void scatter_kernel(const int* __restrict__ edge_list,
                               const float* __restrict__ edge_weight,
                               const float* __restrict__ x) {
    const int e = blockIdx.x * blockDim.x + threadIdx.x;
    if (e >= N_EDGES) return;
    const int src = edge_list[3 * e + 0];
    const int dst = edge_list[3 * e + 1];
    const int rel = edge_list[3 * e + 2];
    const float w = edge_weight[e];

    const float4* xr = reinterpret_cast<const float4*>(x + (size_t)src * IN_DIM);
    float* base = g_num + (size_t)dst * K_DIM + rel * IN_DIM;

#pragma unroll
    for (int i = 0; i < IN_DIM / 4; i++) {
        float4 v = xr[i];
        asm volatile(
            "red.global.add.v4.f32 [%0], {%1, %2, %3, %4};"
            :: "l"(base + i * 4),
               "f"(v.x * w), "f"(v.y * w), "f"(v.z * w), "f"(v.w * w)
            : "memory");
    }
    atomicAdd(g_den + (size_t)dst * N_REL + rel, w);
}

// ---------------------------------------------------------------------------
// Kernel 2: fused normalize + tf32 mma.sync GEMM + bias + ReLU.
//   out[128t, 64] = relu([update | x] @ [Wl ; Ws] + b)
//   8 warps/block, each warp: m16 x n64, K=288 via m16n8k8 tf32 MMA.
//   B fragments pre-packed once per persistent block (tile-invariant).
// ---------------------------------------------------------------------------
#define A_STRIDE 292                           // 292 % 32 == 4 -> conflict-free frags
#define A_FLOATS (128 * A_STRIDE)              // 37376
#define BF_FLOAT2 (N_KSTEP * 8 * 32)           // 9216 float2
#define A_BYTES   (A_FLOATS * 4)               // 149504
#define BF_BYTES  (BF_FLOAT2 * 8)              // 73728
#define DINV_OFF  (A_BYTES + BF_BYTES)         // 223232
#define BIAS_OFF  (DINV_OFF + 128 * N_REL * 4) // 227328
#define SMEM_TOTAL (BIAS_OFF + OUT_DIM * 4)    // 227584

__device__ __forceinline__ void mma_tf32(float c[4], uint32_t a0, uint32_t a1,
                                         uint32_t a2, uint32_t a3,
                                         uint32_t b0, uint32_t b1) {
    asm volatile(
        "mma.sync.aligned.m16n8k8.row.col.f32.tf32.tf32.f32 "
        "{%0,%1,%2,%3}, {%4,%5,%6,%7}, {%8,%9}, {%0,%1,%2,%3};"
        : "+f"(c[0]), "+f"(c[1]), "+f"(c[2]), "+f"(c[3])
        : "r"(a0), "r"(a1), "r"(a2), "r"(a3), "r"(b0), "r"(b1));
}

__global__ __launch_bounds__(256, 1)
void gemm_mma_kernel(const float* __restrict__ x,
                     const float* __restrict__ Wl,
                     const float* __restrict__ bl,
                     const float* __restrict__ Ws,
                     const float* __restrict__ bs,
                     float* __restrict__ out) {
    extern __shared__ char smem[];
    float*  sA    = reinterpret_cast<float*>(smem);
    float2* sBf   = reinterpret_cast<float2*>(smem + A_BYTES);
    float*  sDinv = reinterpret_cast<float*>(smem + DINV_OFF);
    float*  sBias = reinterpret_cast<float*>(smem + BIAS_OFF);

    const int tid  = threadIdx.x;
    const int wid  = tid >> 5;
    const int lane = tid & 31;
    const int g    = lane >> 2;   // group id 0..7
    const int tig  = lane & 3;    // thread in group

    // ---- pack B fragments once (tile-invariant): sBf[(s*8+j)*32+lane] ----
    for (int idx = tid; idx < BF_FLOAT2; idx += 256) {
        const int l  = idx & 31;
        const int j  = (idx >> 5) & 7;
        const int s  = idx >> 8;
        const int gg = l >> 2, tt = l & 3;
        const int n  = j * 8 + gg;
        const int k0 = s * 8 + tt;
        const int k1 = k0 + 4;
        const float v0 = (k0 < K_DIM) ? Wl[(size_t)k0 * OUT_DIM + n]
                                      : Ws[(size_t)(k0 - K_DIM) * OUT_DIM + n];
        const float v1 = (k1 < K_DIM) ? Wl[(size_t)k1 * OUT_DIM + n]
                                      : Ws[(size_t)(k1 - K_DIM) * OUT_DIM + n];
        sBf[idx] = make_float2(to_tf32(v0), to_tf32(v1));
    }
    if (tid < OUT_DIM) sBias[tid] = bl[tid] + bs[tid];
    __syncthreads();

    for (int tile = blockIdx.x; tile < NTILES; tile += gridDim.x) {
        const int node0 = tile * 128;

        // ---- stage 1/den ----
        for (int i = tid; i < 128 * N_REL; i += 256) {
            const int node = node0 + (i >> 3);
            const float d = (node < N_NODES) ? g_den[(size_t)node * N_REL + (i & 7)] : 1.f;
            sDinv[i] = 1.0f / (d + EPS);
        }
        __syncthreads();

        // ---- stage A: update part (cols 0..255), normalized, tf32-rounded ----
        for (int i = tid; i < 128 * 64; i += 256) {
            const int row = i >> 6;
            const int k4  = i & 63;
            const int node = node0 + row;
            float4 v = make_float4(0.f, 0.f, 0.f, 0.f);
            if (node < N_NODES) {
                v = reinterpret_cast<const float4*>(g_num + (size_t)node * K_DIM)[k4];
                const float di = sDinv[row * N_REL + (k4 >> 3)];
                v.x *= di; v.y *= di; v.z *= di; v.w *= di;
            }
            v.x = to_tf32(v.x); v.y = to_tf32(v.y);
            v.z = to_tf32(v.z); v.w = to_tf32(v.w);
            *reinterpret_cast<float4*>(sA + row * A_STRIDE + k4 * 4) = v;
        }
        // ---- stage A: x part (cols 256..287) ----
        for (int i = tid; i < 128 * 8; i += 256) {
            const int row = i >> 3;
            const int c4  = i & 7;
            const int node = node0 + row;
            float4 v = make_float4(0.f, 0.f, 0.f, 0.f);
            if (node < N_NODES)
                v = reinterpret_cast<const float4*>(x + (size_t)node * IN_DIM)[c4];
            v.x = to_tf32(v.x); v.y = to_tf32(v.y);
            v.z = to_tf32(v.z); v.w = to_tf32(v.w);
            *reinterpret_cast<float4*>(sA + row * A_STRIDE + K_DIM + c4 * 4) = v;
        }
        __syncthreads();

        // ---- compute: warp wid handles rows [wid*16, wid*16+16) ----
        float acc[8][4];
#pragma unroll
        for (int j = 0; j < 8; j++)
#pragma unroll
            for (int c = 0; c < 4; c++) acc[j][c] = 0.f;

        const float* arow0 = sA + (wid * 16 + g) * A_STRIDE;
        const float* arow1 = arow0 + 8 * A_STRIDE;

#pragma unroll 4
        for (int s = 0; s < N_KSTEP; s++) {
            const int kb = s * 8 + tig;
            const uint32_t a0 = __float_as_uint(arow0[kb]);
            const uint32_t a1 = __float_as_uint(arow1[kb]);
            const uint32_t a2 = __float_as_uint(arow0[kb + 4]);
            const uint32_t a3 = __float_as_uint(arow1[kb + 4]);
            const float2* bf = sBf + s * 8 * 32 + lane;
#pragma unroll
            for (int j = 0; j < 8; j++) {
                const float2 b = bf[j * 32];
                mma_tf32(acc[j], a0, a1, a2, a3,
                         __float_as_uint(b.x), __float_as_uint(b.y));
            }
        }

        // ---- epilogue: bias + relu + direct global stores (float2) ----
        const int r0 = node0 + wid * 16 + g;
        const int r1 = r0 + 8;
#pragma unroll
        for (int j = 0; j < 8; j++) {
            const int col = j * 8 + tig * 2;
            const float b0 = sBias[col], b1 = sBias[col + 1];
            if (r0 < N_NODES) {
                float2 v = make_float2(fmaxf(acc[j][0] + b0, 0.f),
                                       fmaxf(acc[j][1] + b1, 0.f));
                *reinterpret_cast<float2*>(out + (size_t)r0 * OUT_DIM + col) = v;
            }
            if (r1 < N_NODES) {
                float2 v = make_float2(fmaxf(acc[j][2] + b0, 0.f),
                                       fmaxf(acc[j][3] + b1, 0.f));
                *reinterpret_cast<float2*>(out + (size_t)r1 * OUT_DIM + col) = v;
            }
        }
        __syncthreads();   // protect sA before next tile's staging
    }
}

// ---------------------------------------------------------------------------
// Launch
// ---------------------------------------------------------------------------
extern "C" void kernel_launch(void* const* d_in, const int* in_sizes, int n_in,
                              void* d_out, int out_size) {
    const float* x     = (const float*)d_in[0];
    const int*   edges = (const int*)  d_in[1];
    const float* ew    = (const float*)d_in[2];
    const float* Wl    = (const float*)d_in[3];
    const float* bl    = (const float*)d_in[4];
    const float* Ws    = (const float*)d_in[5];
    const float* bs    = (const float*)d_in[6];
    float*       out   = (float*)d_out;

    // zero accumulators via memset nodes (graph-capturable)
    void* pnum = nullptr; void* pden = nullptr;
    cudaGetSymbolAddress(&pnum, g_num);
    cudaGetSymbolAddress(&pden, g_den);
    cudaMemsetAsync(pnum, 0, (size_t)N_NODES * K_DIM * sizeof(float), 0);
    cudaMemsetAsync(pden, 0, (size_t)N_NODES * N_REL * sizeof(float), 0);

    // edge scatter
    scatter_kernel<<<(N_EDGES + 255) / 256, 256>>>(edges, ew, x);

    // tensor-core (HMMA tf32) GEMM
    cudaFuncSetAttribute(gemm_mma_kernel,
                         cudaFuncAttributeMaxDynamicSharedMemorySize,
                         SMEM_TOTAL);
    gemm_mma_kernel<<<148, 256, SMEM_TOTAL>>>(x, Wl, bl, Ws, bs, out);
}

// round 4
// speedup vs baseline: 1.7701x; 1.2282x over previous
#include <cuda_runtime.h>
#include <cstdint>

#define N_NODES 100000
#define N_EDGES 1600000
#define IN_DIM 32
#define OUT_DIM 64
#define N_REL 8
#define K_DIM (N_REL * IN_DIM)   // 256
#define K_TOT 288
#define N_KSTEP (K_TOT / 8)      // 36
#define EPS 1e-10f

static constexpr int NROWTILES = N_NODES / 16;   // 6250 exact

// Scratch (alloc-free rule: __device__ globals)
__device__ float g_num[(size_t)N_NODES * K_DIM];
__device__ float g_den[(size_t)N_NODES * N_REL];

__device__ __forceinline__ float to_tf32(float v) {
    uint32_t r;
    asm("cvt.rna.tf32.f32 %0, %1;" : "=r"(r) : "f"(v));
    return __uint_as_float(r);
}

// ---------------------------------------------------------------------------
// Kernel 1: edge scatter (unchanged — round-5 target)
// ---------------------------------------------------------------------------
__global__ void scatter_kernel(const int* __restrict__ edge_list,
                               const float* __restrict__ edge_weight,
                               const float* __restrict__ x) {
    const int e = blockIdx.x * blockDim.x + threadIdx.x;
    if (e >= N_EDGES) return;
    const int src = edge_list[3 * e + 0];
    const int dst = edge_list[3 * e + 1];
    const int rel = edge_list[3 * e + 2];
    const float w = edge_weight[e];

    const float4* xr = reinterpret_cast<const float4*>(x + (size_t)src * IN_DIM);
    float* base = g_num + (size_t)dst * K_DIM + rel * IN_DIM;

#pragma unroll
    for (int i = 0; i < IN_DIM / 4; i++) {
        float4 v = xr[i];
        asm volatile(
            "red.global.add.v4.f32 [%0], {%1, %2, %3, %4};"
            :: "l"(base + i * 4),
               "f"(v.x * w), "f"(v.y * w), "f"(v.z * w), "f"(v.w * w)
            : "memory");
    }
    atomicAdd(g_den + (size_t)dst * N_REL + rel, w);
}

// ---------------------------------------------------------------------------
// Kernel 2: warp-autonomous tf32 MMA GEMM.
//   Each warp owns m16 row-tiles; A fragments loaded directly from global
//   with 1/den normalization in registers. B fragments (tile-invariant)
//   staged in SMEM once. No barriers in the main loop.
// ---------------------------------------------------------------------------
#define BF_FLOAT2 (N_KSTEP * 8 * 32)           // 9216 float2
#define BF_BYTES  (BF_FLOAT2 * 8)              // 73728
#define SMEM_TOTAL (BF_BYTES + OUT_DIM * 4)    // + bias

__device__ __forceinline__ void mma_tf32(float c[4], uint32_t a0, uint32_t a1,
                                         uint32_t a2, uint32_t a3,
                                         uint32_t b0, uint32_t b1) {
    asm volatile(
        "mma.sync.aligned.m16n8k8.row.col.f32.tf32.tf32.f32 "
        "{%0,%1,%2,%3}, {%4,%5,%6,%7}, {%8,%9}, {%0,%1,%2,%3};"
        : "+f"(c[0]), "+f"(c[1]), "+f"(c[2]), "+f"(c[3])
        : "r"(a0), "r"(a1), "r"(a2), "r"(a3), "r"(b0), "r"(b1));
}

__global__ __launch_bounds__(512, 1)
void gemm_mma_kernel(const float* __restrict__ x,
                     const float* __restrict__ Wl,
                     const float* __restrict__ bl,
                     const float* __restrict__ Ws,
                     const float* __restrict__ bs,
                     float* __restrict__ out) {
    extern __shared__ char smem[];
    float2* sBf   = reinterpret_cast<float2*>(smem);
    float*  sBias = reinterpret_cast<float*>(smem + BF_BYTES);

    const int tid  = threadIdx.x;
    const int wid  = tid >> 5;
    const int lane = tid & 31;
    const int g    = lane >> 2;
    const int tig  = lane & 3;

    // ---- stage B fragments once: sBf[(s*8+j)*32 + lane] ----
    for (int idx = tid; idx < BF_FLOAT2; idx += 512) {
        const int l  = idx & 31;
        const int j  = (idx >> 5) & 7;
        const int s  = idx >> 8;
        const int gg = l >> 2, tt = l & 3;
        const int n  = j * 8 + gg;
        const int k0 = s * 8 + tt;
        const int k1 = k0 + 4;
        const float v0 = (k0 < K_DIM) ? Wl[(size_t)k0 * OUT_DIM + n]
                                      : Ws[(size_t)(k0 - K_DIM) * OUT_DIM + n];
        const float v1 = (k1 < K_DIM) ? Wl[(size_t)k1 * OUT_DIM + n]
                                      : Ws[(size_t)(k1 - K_DIM) * OUT_DIM + n];
        sBf[idx] = make_float2(to_tf32(v0), to_tf32(v1));
    }
    if (tid < OUT_DIM) sBias[tid] = bl[tid] + bs[tid];
    __syncthreads();

    const int nwarps = gridDim.x * 16;

    for (int t = blockIdx.x * 16 + wid; t < NROWTILES; t += nwarps) {
        const int row0 = t * 16 + g;       // always < N_NODES (exact tiling)
        const int row1 = row0 + 8;

        // ---- 1/den for both rows, all 8 rel-blocks ----
        float dinv0[8], dinv1[8];
        {
            const float4* d0 = reinterpret_cast<const float4*>(g_den + (size_t)row0 * N_REL);
            const float4* d1 = reinterpret_cast<const float4*>(g_den + (size_t)row1 * N_REL);
            float4 a = d0[0], b = d0[1], c = d1[0], d = d1[1];
            dinv0[0] = __fdividef(1.f, a.x + EPS); dinv0[1] = __fdividef(1.f, a.y + EPS);
            dinv0[2] = __fdividef(1.f, a.z + EPS); dinv0[3] = __fdividef(1.f, a.w + EPS);
            dinv0[4] = __fdividef(1.f, b.x + EPS); dinv0[5] = __fdividef(1.f, b.y + EPS);
            dinv0[6] = __fdividef(1.f, b.z + EPS); dinv0[7] = __fdividef(1.f, b.w + EPS);
            dinv1[0] = __fdividef(1.f, c.x + EPS); dinv1[1] = __fdividef(1.f, c.y + EPS);
            dinv1[2] = __fdividef(1.f, c.z + EPS); dinv1[3] = __fdividef(1.f, c.w + EPS);
            dinv1[4] = __fdividef(1.f, d.x + EPS); dinv1[5] = __fdividef(1.f, d.y + EPS);
            dinv1[6] = __fdividef(1.f, d.z + EPS); dinv1[7] = __fdividef(1.f, d.w + EPS);
        }

        float acc[8][4];
#pragma unroll
        for (int j = 0; j < 8; j++)
#pragma unroll
            for (int c = 0; c < 4; c++) acc[j][c] = 0.f;

        const float* A0 = g_num + (size_t)row0 * K_DIM;
        const float* A1 = g_num + (size_t)row1 * K_DIM;

#pragma unroll 8
        for (int s = 0; s < 32; s++) {
            const int k = s * 8 + tig;
            const int b = s >> 2;
            const uint32_t a0 = __float_as_uint(to_tf32(A0[k]     * dinv0[b]));
            const uint32_t a1 = __float_as_uint(to_tf32(A1[k]     * dinv1[b]));
            const uint32_t a2 = __float_as_uint(to_tf32(A0[k + 4] * dinv0[b]));
            const uint32_t a3 = __float_as_uint(to_tf32(A1[k + 4] * dinv1[b]));
            const float2* bf = sBf + s * 256 + lane;
#pragma unroll
            for (int j = 0; j < 8; j++) {
                const float2 bb = bf[j * 32];
                mma_tf32(acc[j], a0, a1, a2, a3,
                         __float_as_uint(bb.x), __float_as_uint(bb.y));
            }
        }

        // ---- x part (K cols 256..287) ----
        const float* X0 = x + (size_t)row0 * IN_DIM;
        const float* X1 = x + (size_t)row1 * IN_DIM;
#pragma unroll
        for (int s = 32; s < 36; s++) {
            const int c = (s - 32) * 8 + tig;
            const uint32_t a0 = __float_as_uint(to_tf32(X0[c]));
            const uint32_t a1 = __float_as_uint(to_tf32(X1[c]));
            const uint32_t a2 = __float_as_uint(to_tf32(X0[c + 4]));
            const uint32_t a3 = __float_as_uint(to_tf32(X1[c + 4]));
            const float2* bf = sBf + s * 256 + lane;
#pragma unroll
            for (int j = 0; j < 8; j++) {
                const float2 bb = bf[j * 32];
                mma_tf32(acc[j], a0, a1, a2, a3,
                         __float_as_uint(bb.x), __float_as_uint(bb.y));
            }
        }

        // ---- epilogue: bias + relu + float2 stores ----
#pragma unroll
        for (int j = 0; j < 8; j++) {
            const int col = j * 8 + tig * 2;
            const float b0 = sBias[col], b1 = sBias[col + 1];
            float2 v0 = make_float2(fmaxf(acc[j][0] + b0, 0.f),
                                    fmaxf(acc[j][1] + b1, 0.f));
            float2 v1 = make_float2(fmaxf(acc[j][2] + b0, 0.f),
                                    fmaxf(acc[j][3] + b1, 0.f));
            *reinterpret_cast<float2*>(out + (size_t)row0 * OUT_DIM + col) = v0;
            *reinterpret_cast<float2*>(out + (size_t)row1 * OUT_DIM + col) = v1;
        }
    }
}

// ---------------------------------------------------------------------------
// Launch
// ---------------------------------------------------------------------------
extern "C" void kernel_launch(void* const* d_in, const int* in_sizes, int n_in,
                              void* d_out, int out_size) {
    const float* x     = (const float*)d_in[0];
    const int*   edges = (const int*)  d_in[1];
    const float* ew    = (const float*)d_in[2];
    const float* Wl    = (const float*)d_in[3];
    const float* bl    = (const float*)d_in[4];
    const float* Ws    = (const float*)d_in[5];
    const float* bs    = (const float*)d_in[6];
    float*       out   = (float*)d_out;

    void* pnum = nullptr; void* pden = nullptr;
    cudaGetSymbolAddress(&pnum, g_num);
    cudaGetSymbolAddress(&pden, g_den);
    cudaMemsetAsync(pnum, 0, (size_t)N_NODES * K_DIM * sizeof(float), 0);
    cudaMemsetAsync(pden, 0, (size_t)N_NODES * N_REL * sizeof(float), 0);

    scatter_kernel<<<(N_EDGES + 255) / 256, 256>>>(edges, ew, x);

    cudaFuncSetAttribute(gemm_mma_kernel,
                         cudaFuncAttributeMaxDynamicSharedMemorySize,
                         SMEM_TOTAL);
    gemm_mma_kernel<<<148, 512, SMEM_TOTAL>>>(x, Wl, bl, Ws, bs, out);
}